// round 12
// baseline (speedup 1.0000x reference)
#include <cuda_runtime.h>
#include <cuda_fp16.h>
#include <cstdint>

// ---------------------------------------------------------------------------
// QuantizedLinear NF4 on plain sm_103 target:
//   out[M,N] = fp16 mma.sync GEMM( half(x), half(dequant_nf4*absmax) ) + bias
//   M = 8192, K = 4096, N = 4096
// R10/R11: reorder MMA issue so the two k16-chunks of each accumulator are 32
// instructions apart (was back-to-back -> ~11 cyc/HMMA RAW stall).
// ---------------------------------------------------------------------------

#define M_DIM 8192
#define K_DIM 4096
#define N_DIM 4096

#define BM 256
#define BN 128
#define KTILES (K_DIM / 64)            // 64 mainloop iterations (64 k per stage)
#define A_T32 (BM * 32 * 2)            // 16384 B  (256 rows x 64 B)
#define B_T32 (BN * 32 * 2)            // 8192 B   (128 rows x 64 B)
#define A_STG (2 * A_T32)              // 32768 B
#define B_STG (2 * B_T32)              // 16384 B
#define STG (A_STG + B_STG)            // 49152 B
#define STAGES 4
#define GEMM_SMEM (STAGES * STG)       // 196608 B

// Scratch (allocation-free rule: __device__ globals), fp16 tile-contiguous:
//  g_Ah: [bm=32][t32=128][row=256][32 halves, k-permuted: chunk c pos p -> k=8*(p>>1)+2c+(p&1)]
//  g_Wh: [bn=32][t32=128][row=128][32 halves, same permutation]
__device__ __half g_Ah[(size_t)M_DIM * K_DIM];
__device__ __half g_Wh[(size_t)N_DIM * K_DIM];

__constant__ float c_nf4[16] = {
    -1.0f, -0.6961928009986877f, -0.5250730514526367f, -0.39491748809814453f,
    -0.28444138169288635f, -0.18477343022823334f, -0.09105003625154495f, 0.0f,
    0.07958029955625534f, 0.16093020141124725f, 0.24611230194568634f,
    0.33791524171829224f, 0.44070982933044434f, 0.5626170039176941f,
    0.7229568362236023f, 1.0f};

// ---------------------------------------------------------------------------
// helpers
// ---------------------------------------------------------------------------
__device__ __forceinline__ uint32_t h2_u32(__half2 h) {
    uint32_t u;
    __builtin_memcpy(&u, &h, 4);
    return u;
}

__device__ __forceinline__ uint32_t smem_u32(const void* p) {
    uint32_t a;
    asm("{ .reg .u64 t; cvta.to.shared.u64 t, %1; cvt.u32.u64 %0, t; }"
        : "=r"(a) : "l"(p));
    return a;
}

__device__ __forceinline__ void bulk_g2s(uint32_t dst, const void* src,
                                         uint32_t bytes, uint32_t mbar) {
    asm volatile(
        "cp.async.bulk.shared::cta.global.mbarrier::complete_tx::bytes "
        "[%0], [%1], %2, [%3];"
        :: "r"(dst), "l"(src), "r"(bytes), "r"(mbar) : "memory");
}

#define MBARRIER_INIT(addr, cnt) \
    asm volatile("mbarrier.init.shared.b64 [%0], %1;" \
                 :: "r"((uint32_t)(addr)), "r"((uint32_t)(cnt)) : "memory")
#define MBARRIER_EXPECT_TX(addr, bytes) \
    asm volatile("mbarrier.arrive.expect_tx.shared.b64 _, [%0], %1;" \
                 :: "r"((uint32_t)(addr)), "r"((uint32_t)(bytes)) : "memory")

#define MBARRIER_WAIT_PARITY(mbar_addr, parity) do { \
    uint32_t _m = (uint32_t)(mbar_addr); \
    uint32_t _p = (uint32_t)(parity); \
    uint32_t _done; \
    asm volatile( \
        "{\n\t.reg .pred p;\n\t" \
        "mbarrier.try_wait.parity.acquire.cta.shared::cta.b64 p, [%1], %2;\n\t" \
        "selp.b32 %0, 1, 0, p;\n\t}" \
        : "=r"(_done) : "r"(_m), "r"(_p) : "memory"); \
    if (!_done) { \
        asm volatile( \
            "{\n\t.reg .pred P1;\n\t" \
            "WL_%=:\n\t" \
            "mbarrier.try_wait.parity.acquire.cta.shared::cta.b64 P1, [%0], %1, 0x989680;\n\t" \
            "@P1 bra.uni WD_%=;\n\t" \
            "bra.uni WL_%=;\n\t" \
            "WD_%=:\n\t}" \
            :: "r"(_m), "r"(_p) : "memory"); \
    } \
} while (0)

__device__ __forceinline__ void lds128(uint32_t addr, uint32_t& x, uint32_t& y,
                                       uint32_t& z, uint32_t& w) {
    asm volatile("ld.shared.v4.b32 {%0,%1,%2,%3}, [%4];"
                 : "=r"(x), "=r"(y), "=r"(z), "=r"(w) : "r"(addr));
}

// D += A*B, f16 m16n8k16, f32 accumulate.
__device__ __forceinline__ void mma_f16(float* d, uint32_t a0, uint32_t a1,
                                        uint32_t a2, uint32_t a3,
                                        uint32_t b0, uint32_t b1) {
    asm volatile(
        "mma.sync.aligned.m16n8k16.row.col.f32.f16.f16.f32 "
        "{%0,%1,%2,%3}, {%4,%5,%6,%7}, {%8,%9}, {%0,%1,%2,%3};"
        : "+f"(d[0]), "+f"(d[1]), "+f"(d[2]), "+f"(d[3])
        : "r"(a0), "r"(a1), "r"(a2), "r"(a3), "r"(b0), "r"(b1));
}

// ---------------------------------------------------------------------------
// Prepass 1: x -> fp16 g_Ah. Each thread builds one 16B chunk:
//   chunk c of (row m, tile t) holds k = 8q + 2c + r  (q=0..3, r=0..1)
// ---------------------------------------------------------------------------
__global__ __launch_bounds__(256) void round_a_kernel(const float* __restrict__ x) {
    size_t id = (size_t)blockIdx.x * 256 + threadIdx.x; // 16B chunk index
    size_t m = id >> 9;       // 512 chunks per row
    int rem = (int)(id & 511);
    int t = rem >> 2;         // 32-k tile
    int cc = rem & 3;         // chunk
    const float* src = x + m * K_DIM + t * 32 + 2 * cc;
    float2 v0 = *reinterpret_cast<const float2*>(src + 0);
    float2 v1 = *reinterpret_cast<const float2*>(src + 8);
    float2 v2 = *reinterpret_cast<const float2*>(src + 16);
    float2 v3 = *reinterpret_cast<const float2*>(src + 24);
    uint4 o;
    o.x = h2_u32(__floats2half2_rn(v0.x, v0.y));
    o.y = h2_u32(__floats2half2_rn(v1.x, v1.y));
    o.z = h2_u32(__floats2half2_rn(v2.x, v2.y));
    o.w = h2_u32(__floats2half2_rn(v3.x, v3.y));
    // dst (uint4 units): [m>>8][t][m&255][cc]
    size_t dst = ((size_t)(m >> 8) * 128 + t) * 1024 + (size_t)(m & 255) * 4 + cc;
    reinterpret_cast<uint4*>(g_Ah)[dst] = o;
}

// ---------------------------------------------------------------------------
// Prepass 2: NF4 dequant -> fp16 g_Wh, same layout.
// k = 8q+2c+r; byte index = 4q+c within the tile; r=0 -> high nibble (even k).
// ---------------------------------------------------------------------------
__global__ __launch_bounds__(256) void dequant_kernel(const int* __restrict__ packed,
                                                      const float* __restrict__ absmax) {
    size_t id = (size_t)blockIdx.x * 256 + threadIdx.x;
    size_t o_row = id >> 9;
    int rem = (int)(id & 511);
    int t = rem >> 2;
    int cc = rem & 3;
    float am = __ldg(&absmax[o_row]);
    const int* pb = packed + o_row * (K_DIM / 2) + t * 16 + cc;
    uint4 o;
    uint32_t* op = &o.x;
#pragma unroll
    for (int q = 0; q < 4; q++) {
        int b = pb[q * 4];
        float hi = c_nf4[(b >> 4) & 15] * am; // even k
        float lo = c_nf4[b & 15] * am;        // odd k
        op[q] = h2_u32(__floats2half2_rn(hi, lo));
    }
    // dst (uint4 units): [o>>7][t][o&127][cc]
    size_t dst = ((size_t)(o_row >> 7) * 128 + t) * 512 + (size_t)(o_row & 127) * 4 + cc;
    reinterpret_cast<uint4*>(g_Wh)[dst] = o;
}

// ---------------------------------------------------------------------------
// GEMM: 256x128 CTA tile, 64-k stages (2 sub-tiles), 4-stage bulk ring,
// 8 warps (64x64 each). MMA issue reordered: chunk0 x32 then chunk1 x32.
// ---------------------------------------------------------------------------
__global__ __launch_bounds__(256, 1) void gemm_kernel(const float* __restrict__ bias,
                                                      float* __restrict__ out) {
    extern __shared__ __align__(1024) char smem[];
    __shared__ __align__(8) uint64_t mbar_store[STAGES];
    const uint32_t sbase = smem_u32(smem);
    const uint32_t mbar0 = smem_u32(mbar_store);

    const int tid = threadIdx.x;
    const int wid = tid >> 5;
    const int lane = tid & 31;
    const int bn = blockIdx.x;
    const int bm = blockIdx.y;

    if (tid == 0) {
#pragma unroll
        for (int s = 0; s < STAGES; s++) MBARRIER_INIT(mbar0 + s * 8, 1);
    }
    __syncthreads();

    const char* aTile = (const char*)g_Ah + (size_t)bm * ((size_t)KTILES * A_STG);
    const char* bTile = (const char*)g_Wh + (size_t)bn * ((size_t)KTILES * B_STG);

    auto issue = [&](int kt) {
        const int s = kt & (STAGES - 1);
        const uint32_t sb = sbase + (uint32_t)s * STG;
        const uint32_t mb = mbar0 + (uint32_t)s * 8;
        MBARRIER_EXPECT_TX(mb, STG);
        bulk_g2s(sb, aTile + (size_t)kt * A_STG, A_STG, mb);
        bulk_g2s(sb + A_STG, bTile + (size_t)kt * B_STG, B_STG, mb);
    };

    if (tid == 0) {
#pragma unroll
        for (int s = 0; s < STAGES - 1; s++) issue(s);
    }

    // ---- compute-side addressing ----
    const int wm = wid & 3;             // 4 m-warps
    const int wn = wid >> 2;            // 2 n-warps
    const int c = lane & 3;             // k-pair selector
    const int rq = lane >> 2;           // row-in-8

    const uint32_t aCmp = (uint32_t)((wm * 64 + rq) * 64 + c * 16); // +i*1024, +512 row+8
    const uint32_t bCmp = (uint32_t)(A_STG + (wn * 64 + rq) * 64 + c * 16); // +nf*512

    float acc[4][8][4];
#pragma unroll
    for (int i = 0; i < 4; i++)
#pragma unroll
        for (int nf = 0; nf < 8; nf++)
#pragma unroll
            for (int q = 0; q < 4; q++) acc[i][nf][q] = 0.0f;

    // ---- mainloop ----
#pragma unroll 1
    for (int kt = 0; kt < KTILES; ++kt) {
        __syncthreads();
        if (tid == 0 && kt + STAGES - 1 < KTILES) issue(kt + STAGES - 1);

        MBARRIER_WAIT_PARITY(mbar0 + (uint32_t)(kt & (STAGES - 1)) * 8,
                             (uint32_t)(kt >> 2) & 1u);

        const uint32_t sb = sbase + (uint32_t)(kt & (STAGES - 1)) * STG;

#pragma unroll
        for (int st = 0; st < 2; st++) {
            const uint32_t ab = sb + (uint32_t)st * A_T32 + aCmp;
            const uint32_t bbbase = sb + (uint32_t)st * B_T32 + bCmp;

            uint32_t bb[8][4];
#pragma unroll
            for (int nf = 0; nf < 8; nf++)
                lds128(bbbase + nf * 512, bb[nf][0], bb[nf][1], bb[nf][2], bb[nf][3]);

            uint32_t aL[4][4], aH[4][4];
#pragma unroll
            for (int i = 0; i < 4; i++) {
                lds128(ab + i * 1024, aL[i][0], aL[i][1], aL[i][2], aL[i][3]);       // row rq
                lds128(ab + i * 1024 + 512, aH[i][0], aH[i][1], aH[i][2], aH[i][3]); // row rq+8
            }

            // pass 0: all k16-chunk-0 MMAs (32 per warp, no acc reuse inside)
#pragma unroll
            for (int nf = 0; nf < 8; nf++)
#pragma unroll
                for (int i = 0; i < 4; i++)
                    mma_f16(acc[i][nf], aL[i][0], aH[i][0], aL[i][1], aH[i][1],
                            bb[nf][0], bb[nf][1]);

            // pass 1: all k16-chunk-1 MMAs (acc reuse distance = 32 instrs)
#pragma unroll
            for (int nf = 0; nf < 8; nf++)
#pragma unroll
                for (int i = 0; i < 4; i++)
                    mma_f16(acc[i][nf], aL[i][2], aH[i][2], aL[i][3], aH[i][3],
                            bb[nf][2], bb[nf][3]);
        }
    }

    // ---- epilogue: +bias, write fp32 ----
    const int mBase = bm * BM + wm * 64;
    const int nBase = bn * BN + wn * 64;

    float2 bv[8];
#pragma unroll
    for (int nf = 0; nf < 8; nf++) {
        int n0 = nBase + nf * 8 + 2 * c;
        bv[nf] = *reinterpret_cast<const float2*>(bias + n0);
    }

#pragma unroll
    for (int i = 0; i < 4; i++) {
        int m0 = mBase + i * 16 + rq;
        float* o0 = out + (size_t)m0 * N_DIM;
        float* o1 = o0 + (size_t)8 * N_DIM;
#pragma unroll
        for (int nf = 0; nf < 8; nf++) {
            int n0 = nBase + nf * 8 + 2 * c;
            float2 v0, v1;
            v0.x = acc[i][nf][0] + bv[nf].x;
            v0.y = acc[i][nf][1] + bv[nf].y;
            v1.x = acc[i][nf][2] + bv[nf].x;
            v1.y = acc[i][nf][3] + bv[nf].y;
            *reinterpret_cast<float2*>(o0 + n0) = v0;
            *reinterpret_cast<float2*>(o1 + n0) = v1;
        }
    }
}

// ---------------------------------------------------------------------------
// Launch
// ---------------------------------------------------------------------------
extern "C" void kernel_launch(void* const* d_in, const int* in_sizes, int n_in,
                              void* d_out, int out_size) {
    const float* x = (const float*)d_in[0];
    const int* packed = (const int*)d_in[1];
    const float* absmax = (const float*)d_in[2];
    const float* bias = (const float*)d_in[3];
    float* out = (float*)d_out;

    cudaFuncSetAttribute(gemm_kernel, cudaFuncAttributeMaxDynamicSharedMemorySize,
                         GEMM_SMEM);

    round_a_kernel<<<(int)(((size_t)M_DIM * 512) / 256), 256>>>(x);
    dequant_kernel<<<(int)(((size_t)N_DIM * 512) / 256), 256>>>(packed, absmax);

    dim3 grid(N_DIM / BN, M_DIM / BM); // (32, 32)
    gemm_kernel<<<grid, 256, GEMM_SMEM>>>(bias, out);
}

// round 13
// speedup vs baseline: 1.6260x; 1.6260x over previous
#include <cuda_runtime.h>
#include <cuda_fp16.h>
#include <cstdint>

// ---------------------------------------------------------------------------
// QuantizedLinear NF4 on plain sm_103 target:
//   out[M,N] = fp16 mma.sync GEMM( half(x), half(dequant_nf4*absmax) ) + bias
//   M = 8192, K = 4096, N = 4096
// R12: revert R11 reorder (caused spills). Retile 128x128 CTA / 64x32 warp,
// 3-stage ring, occupancy 2 (4 warps/SMSP) to hide per-iteration overhead.
// ---------------------------------------------------------------------------

#define M_DIM 8192
#define K_DIM 4096
#define N_DIM 4096

#define BM 128
#define BN 128
#define KTILES (K_DIM / 64)            // 64 mainloop iterations (64 k per stage)
#define A_SUB 8192                     // 128 rows x 64 B per 32-k subtile
#define B_SUB 8192
#define A_STG (2 * A_SUB)              // 16384 B per stage
#define B_STG (2 * B_SUB)              // 16384 B
#define STG (A_STG + B_STG)            // 32768 B
#define STAGES 3
#define GEMM_SMEM (STAGES * STG)       // 98304 B

// Scratch (allocation-free rule: __device__ globals), fp16 tile-contiguous:
//  g_Ah: [bm128=64][t32=128][row=128][32 halves, k-permuted: chunk c pos p -> k=8*(p>>1)+2c+(p&1)]
//  g_Wh: [bn128=32][t32=128][row=128][32 halves, same permutation]
__device__ __half g_Ah[(size_t)M_DIM * K_DIM];
__device__ __half g_Wh[(size_t)N_DIM * K_DIM];

__constant__ float c_nf4[16] = {
    -1.0f, -0.6961928009986877f, -0.5250730514526367f, -0.39491748809814453f,
    -0.28444138169288635f, -0.18477343022823334f, -0.09105003625154495f, 0.0f,
    0.07958029955625534f, 0.16093020141124725f, 0.24611230194568634f,
    0.33791524171829224f, 0.44070982933044434f, 0.5626170039176941f,
    0.7229568362236023f, 1.0f};

// ---------------------------------------------------------------------------
// helpers
// ---------------------------------------------------------------------------
__device__ __forceinline__ uint32_t h2_u32(__half2 h) {
    uint32_t u;
    __builtin_memcpy(&u, &h, 4);
    return u;
}

__device__ __forceinline__ uint32_t smem_u32(const void* p) {
    uint32_t a;
    asm("{ .reg .u64 t; cvta.to.shared.u64 t, %1; cvt.u32.u64 %0, t; }"
        : "=r"(a) : "l"(p));
    return a;
}

__device__ __forceinline__ void bulk_g2s(uint32_t dst, const void* src,
                                         uint32_t bytes, uint32_t mbar) {
    asm volatile(
        "cp.async.bulk.shared::cta.global.mbarrier::complete_tx::bytes "
        "[%0], [%1], %2, [%3];"
        :: "r"(dst), "l"(src), "r"(bytes), "r"(mbar) : "memory");
}

#define MBARRIER_INIT(addr, cnt) \
    asm volatile("mbarrier.init.shared.b64 [%0], %1;" \
                 :: "r"((uint32_t)(addr)), "r"((uint32_t)(cnt)) : "memory")
#define MBARRIER_EXPECT_TX(addr, bytes) \
    asm volatile("mbarrier.arrive.expect_tx.shared.b64 _, [%0], %1;" \
                 :: "r"((uint32_t)(addr)), "r"((uint32_t)(bytes)) : "memory")

#define MBARRIER_WAIT_PARITY(mbar_addr, parity) do { \
    uint32_t _m = (uint32_t)(mbar_addr); \
    uint32_t _p = (uint32_t)(parity); \
    uint32_t _done; \
    asm volatile( \
        "{\n\t.reg .pred p;\n\t" \
        "mbarrier.try_wait.parity.acquire.cta.shared::cta.b64 p, [%1], %2;\n\t" \
        "selp.b32 %0, 1, 0, p;\n\t}" \
        : "=r"(_done) : "r"(_m), "r"(_p) : "memory"); \
    if (!_done) { \
        asm volatile( \
            "{\n\t.reg .pred P1;\n\t" \
            "WL_%=:\n\t" \
            "mbarrier.try_wait.parity.acquire.cta.shared::cta.b64 P1, [%0], %1, 0x989680;\n\t" \
            "@P1 bra.uni WD_%=;\n\t" \
            "bra.uni WL_%=;\n\t" \
            "WD_%=:\n\t}" \
            :: "r"(_m), "r"(_p) : "memory"); \
    } \
} while (0)

__device__ __forceinline__ void lds128(uint32_t addr, uint32_t& x, uint32_t& y,
                                       uint32_t& z, uint32_t& w) {
    asm volatile("ld.shared.v4.b32 {%0,%1,%2,%3}, [%4];"
                 : "=r"(x), "=r"(y), "=r"(z), "=r"(w) : "r"(addr));
}

// D += A*B, f16 m16n8k16, f32 accumulate.
__device__ __forceinline__ void mma_f16(float* d, uint32_t a0, uint32_t a1,
                                        uint32_t a2, uint32_t a3,
                                        uint32_t b0, uint32_t b1) {
    asm volatile(
        "mma.sync.aligned.m16n8k16.row.col.f32.f16.f16.f32 "
        "{%0,%1,%2,%3}, {%4,%5,%6,%7}, {%8,%9}, {%0,%1,%2,%3};"
        : "+f"(d[0]), "+f"(d[1]), "+f"(d[2]), "+f"(d[3])
        : "r"(a0), "r"(a1), "r"(a2), "r"(a3), "r"(b0), "r"(b1));
}

// ---------------------------------------------------------------------------
// Prepass 1: x -> fp16 g_Ah. Each thread builds one 16B chunk:
//   chunk c of (row m, tile t) holds k = 8q + 2c + r  (q=0..3, r=0..1)
// ---------------------------------------------------------------------------
__global__ __launch_bounds__(256) void round_a_kernel(const float* __restrict__ x) {
    size_t id = (size_t)blockIdx.x * 256 + threadIdx.x; // 16B chunk index
    size_t m = id >> 9;       // 512 chunks per row
    int rem = (int)(id & 511);
    int t = rem >> 2;         // 32-k tile
    int cc = rem & 3;         // chunk
    const float* src = x + m * K_DIM + t * 32 + 2 * cc;
    float2 v0 = *reinterpret_cast<const float2*>(src + 0);
    float2 v1 = *reinterpret_cast<const float2*>(src + 8);
    float2 v2 = *reinterpret_cast<const float2*>(src + 16);
    float2 v3 = *reinterpret_cast<const float2*>(src + 24);
    uint4 o;
    o.x = h2_u32(__floats2half2_rn(v0.x, v0.y));
    o.y = h2_u32(__floats2half2_rn(v1.x, v1.y));
    o.z = h2_u32(__floats2half2_rn(v2.x, v2.y));
    o.w = h2_u32(__floats2half2_rn(v3.x, v3.y));
    // dst (uint4 units): [m>>7][t][m&127][cc]  (128-row blocks)
    size_t dst = ((size_t)(m >> 7) * 128 + t) * 512 + (size_t)(m & 127) * 4 + cc;
    reinterpret_cast<uint4*>(g_Ah)[dst] = o;
}

// ---------------------------------------------------------------------------
// Prepass 2: NF4 dequant -> fp16 g_Wh, same layout.
// k = 8q+2c+r; byte index = 4q+c within the tile; r=0 -> high nibble (even k).
// ---------------------------------------------------------------------------
__global__ __launch_bounds__(256) void dequant_kernel(const int* __restrict__ packed,
                                                      const float* __restrict__ absmax) {
    size_t id = (size_t)blockIdx.x * 256 + threadIdx.x;
    size_t o_row = id >> 9;
    int rem = (int)(id & 511);
    int t = rem >> 2;
    int cc = rem & 3;
    float am = __ldg(&absmax[o_row]);
    const int* pb = packed + o_row * (K_DIM / 2) + t * 16 + cc;
    uint4 o;
    uint32_t* op = &o.x;
#pragma unroll
    for (int q = 0; q < 4; q++) {
        int b = pb[q * 4];
        float hi = c_nf4[(b >> 4) & 15] * am; // even k
        float lo = c_nf4[b & 15] * am;        // odd k
        op[q] = h2_u32(__floats2half2_rn(hi, lo));
    }
    // dst (uint4 units): [o>>7][t][o&127][cc]
    size_t dst = ((size_t)(o_row >> 7) * 128 + t) * 512 + (size_t)(o_row & 127) * 4 + cc;
    reinterpret_cast<uint4*>(g_Wh)[dst] = o;
}

// ---------------------------------------------------------------------------
// GEMM: 128x128 CTA tile, 64-k stages (2 sub-tiles), 3-stage bulk ring,
// 8 warps (64x32 each), occupancy 2.
// ---------------------------------------------------------------------------
__global__ __launch_bounds__(256, 2) void gemm_kernel(const float* __restrict__ bias,
                                                      float* __restrict__ out) {
    extern __shared__ __align__(1024) char smem[];
    __shared__ __align__(8) uint64_t mbar_store[STAGES];
    const uint32_t sbase = smem_u32(smem);
    const uint32_t mbar0 = smem_u32(mbar_store);

    const int tid = threadIdx.x;
    const int wid = tid >> 5;
    const int lane = tid & 31;
    const int bn = blockIdx.x;
    const int bm = blockIdx.y;

    if (tid == 0) {
#pragma unroll
        for (int s = 0; s < STAGES; s++) MBARRIER_INIT(mbar0 + s * 8, 1);
    }
    __syncthreads();

    const char* aTile = (const char*)g_Ah + (size_t)bm * ((size_t)KTILES * A_STG);
    const char* bTile = (const char*)g_Wh + (size_t)bn * ((size_t)KTILES * B_STG);

    auto issue = [&](int kt, int s) {
        const uint32_t sb = sbase + (uint32_t)s * STG;
        const uint32_t mb = mbar0 + (uint32_t)s * 8;
        MBARRIER_EXPECT_TX(mb, STG);
        bulk_g2s(sb, aTile + (size_t)kt * A_STG, A_STG, mb);
        bulk_g2s(sb + A_STG, bTile + (size_t)kt * B_STG, B_STG, mb);
    };

    if (tid == 0) {
#pragma unroll
        for (int s = 0; s < STAGES - 1; s++) issue(s, s);
    }

    // ---- compute-side addressing ----
    const int wm = wid & 1;             // 2 m-warps (64 rows each)
    const int wn = wid >> 1;            // 4 n-warps (32 cols each)
    const int c = lane & 3;             // k-pair selector
    const int rq = lane >> 2;           // row-in-8

    const uint32_t aCmp = (uint32_t)((wm * 64 + rq) * 64 + c * 16); // +i*1024, +512 row+8
    const uint32_t bCmp = (uint32_t)(A_STG + (wn * 32 + rq) * 64 + c * 16); // +nf*512

    float acc[4][4][4];
#pragma unroll
    for (int i = 0; i < 4; i++)
#pragma unroll
        for (int nf = 0; nf < 4; nf++)
#pragma unroll
            for (int q = 0; q < 4; q++) acc[i][nf][q] = 0.0f;

    // stage/phase counters (3 stages => no power-of-2 masking)
    int cs = 0, cp = 0;        // consumer stage, phase
    int fs = STAGES - 1;       // next fill stage (tid 0 only)

    // ---- mainloop ----
#pragma unroll 1
    for (int kt = 0; kt < KTILES; ++kt) {
        __syncthreads();
        if (tid == 0 && kt + STAGES - 1 < KTILES) issue(kt + STAGES - 1, fs);
        fs = (fs + 1 == STAGES) ? 0 : fs + 1;

        MBARRIER_WAIT_PARITY(mbar0 + (uint32_t)cs * 8, (uint32_t)cp);

        const uint32_t sb = sbase + (uint32_t)cs * STG;

#pragma unroll
        for (int st = 0; st < 2; st++) {
            const uint32_t ab = sb + (uint32_t)st * A_SUB + aCmp;
            const uint32_t bbbase = sb + (uint32_t)st * B_SUB + bCmp;

            uint32_t bb[4][4];
#pragma unroll
            for (int nf = 0; nf < 4; nf++)
                lds128(bbbase + nf * 512, bb[nf][0], bb[nf][1], bb[nf][2], bb[nf][3]);

#pragma unroll
            for (int i = 0; i < 4; i++) {
                uint32_t aL[4], aH[4];
                lds128(ab + i * 1024, aL[0], aL[1], aL[2], aL[3]);        // row rq
                lds128(ab + i * 1024 + 512, aH[0], aH[1], aH[2], aH[3]);  // row rq+8
#pragma unroll
                for (int nf = 0; nf < 4; nf++) {
                    // k16 chunk 0: pairs q0,q1
                    mma_f16(acc[i][nf], aL[0], aH[0], aL[1], aH[1],
                            bb[nf][0], bb[nf][1]);
                    // k16 chunk 1: pairs q2,q3
                    mma_f16(acc[i][nf], aL[2], aH[2], aL[3], aH[3],
                            bb[nf][2], bb[nf][3]);
                }
            }
        }

        cs = (cs + 1 == STAGES) ? 0 : cs + 1;
        cp ^= (cs == 0);
    }

    // ---- epilogue: +bias, write fp32 ----
    const int mBase = bm * BM + wm * 64;
    const int nBase = bn * BN + wn * 32;

    float2 bv[4];
#pragma unroll
    for (int nf = 0; nf < 4; nf++) {
        int n0 = nBase + nf * 8 + 2 * c;
        bv[nf] = *reinterpret_cast<const float2*>(bias + n0);
    }

#pragma unroll
    for (int i = 0; i < 4; i++) {
        int m0 = mBase + i * 16 + rq;
        float* o0 = out + (size_t)m0 * N_DIM;
        float* o1 = o0 + (size_t)8 * N_DIM;
#pragma unroll
        for (int nf = 0; nf < 4; nf++) {
            int n0 = nBase + nf * 8 + 2 * c;
            float2 v0, v1;
            v0.x = acc[i][nf][0] + bv[nf].x;
            v0.y = acc[i][nf][1] + bv[nf].y;
            v1.x = acc[i][nf][2] + bv[nf].x;
            v1.y = acc[i][nf][3] + bv[nf].y;
            *reinterpret_cast<float2*>(o0 + n0) = v0;
            *reinterpret_cast<float2*>(o1 + n0) = v1;
        }
    }
}

// ---------------------------------------------------------------------------
// Launch
// ---------------------------------------------------------------------------
extern "C" void kernel_launch(void* const* d_in, const int* in_sizes, int n_in,
                              void* d_out, int out_size) {
    const float* x = (const float*)d_in[0];
    const int* packed = (const int*)d_in[1];
    const float* absmax = (const float*)d_in[2];
    const float* bias = (const float*)d_in[3];
    float* out = (float*)d_out;

    cudaFuncSetAttribute(gemm_kernel, cudaFuncAttributeMaxDynamicSharedMemorySize,
                         GEMM_SMEM);

    round_a_kernel<<<(int)(((size_t)M_DIM * 512) / 256), 256>>>(x);
    dequant_kernel<<<(int)(((size_t)N_DIM * 512) / 256), 256>>>(packed, absmax);

    dim3 grid(N_DIM / BN, M_DIM / BM); // (32, 64)
    gemm_kernel<<<grid, 256, GEMM_SMEM>>>(bias, out);
}